// round 7
// baseline (speedup 1.0000x reference)
#include <cuda_runtime.h>
#include <cstdint>

// ============================================================================
// QKV projection as one tf32 mma.sync GEMM (baseline PTX; tcgen05 rejected by
// this toolchain's .target sm_103):
//   C[16384, 12288] = A[16384,4096] @ B[12288,4096]^T
// A = hidden_states (row-major), B = qkv_proj (row-major), RoPE = identity.
// Output: 3 column sections of C -> q|k|v concatenated fp32 regions.
//
// R5 changes vs R4 (7219us, tensor 75% / issue 21%):
//  - single __syncthreads per k-tile (CUTLASS multistage order:
//    wait_group(S-2) -> barrier -> prefetch+commit -> compute) — halves the
//    per-iteration pipeline bubble that capped tensor at 75%.
//  - cvt.rna.tf32 restored on B fragments only (32/ktile/warp): cuts tf32
//    truncation error roughly in half for 2x rel_err margin, ~2% issue cost.
// ============================================================================

static constexpr int MDIM = 16384;
static constexpr int NDIM = 12288;
static constexpr int KDIM = 4096;

static constexpr int BM = 256;
static constexpr int BN = 128;
static constexpr int BK = 32;                  // 32 fp32 = 128 B row
static constexpr int KTILES = KDIM / BK;       // 128
static constexpr int STAGES = 4;
static constexpr int A_BYTES = BM * BK * 4;    // 32 KB
static constexpr int B_BYTES = BN * BK * 4;    // 16 KB
static constexpr int STAGE_BYTES = A_BYTES + B_BYTES;      // 48 KB
static constexpr int SMEM_TOTAL = STAGES * STAGE_BYTES;    // 192 KB
static constexpr int M_TILES = MDIM / BM;      // 64
static constexpr int N_TILES = NDIM / BN;      // 96
static constexpr int PANEL_M = 8;              // L2 rasterization panel
static constexpr int NTHREADS = 512;

__device__ __forceinline__ uint32_t smem_u32(const void* p) {
    uint32_t a;
    asm("{ .reg .u64 t; cvta.to.shared.u64 t, %1; cvt.u32.u64 %0, t; }"
        : "=r"(a) : "l"(p));
    return a;
}

__device__ __forceinline__ void cpa16(uint32_t dst, const void* src) {
    asm volatile("cp.async.cg.shared.global [%0], [%1], 16;" :: "r"(dst), "l"(src));
}

__device__ __forceinline__ uint32_t f2tf32(uint32_t bits) {
    uint32_t o;
    asm("cvt.rna.tf32.f32 %0, %1;" : "=r"(o) : "f"(__uint_as_float(bits)));
    return o;
}

__device__ __forceinline__ void ldsm_x4(uint32_t& r0, uint32_t& r1,
                                        uint32_t& r2, uint32_t& r3, uint32_t addr) {
    asm volatile("ldmatrix.sync.aligned.m8n8.x4.shared.b16 {%0,%1,%2,%3}, [%4];"
                 : "=r"(r0), "=r"(r1), "=r"(r2), "=r"(r3) : "r"(addr));
}

__device__ __forceinline__ void mma_tf32(float& c0, float& c1, float& c2, float& c3,
                                         uint32_t a0, uint32_t a1, uint32_t a2,
                                         uint32_t a3, uint32_t b0, uint32_t b1) {
    asm volatile(
        "mma.sync.aligned.m16n8k8.row.col.f32.tf32.tf32.f32 "
        "{%0,%1,%2,%3}, {%4,%5,%6,%7}, {%8,%9}, {%0,%1,%2,%3};"
        : "+f"(c0), "+f"(c1), "+f"(c2), "+f"(c3)
        : "r"(a0), "r"(a1), "r"(a2), "r"(a3), "r"(b0), "r"(b1));
}

__global__ void __launch_bounds__(NTHREADS, 1)
qkv_tf32_kernel(const float* __restrict__ A, const float* __restrict__ B,
                float* __restrict__ O) {
    extern __shared__ __align__(1024) char smem[];
    const uint32_t sbase = smem_u32(smem);
    const int tid = threadIdx.x;
    const int wid = tid >> 5;
    const int lid = tid & 31;
    const int wr = wid & 3;    // warp row: m-offset wr*64
    const int wc = wid >> 2;   // warp col: n-offset wc*32

    // Panel-swizzled tile mapping (8 m-tiles fast, n slow) for L2 reuse.
    const int bid = blockIdx.x;
    const int panel = bid / (PANEL_M * N_TILES);
    const int rr = bid % (PANEL_M * N_TILES);
    const int mt = panel * PANEL_M + (rr % PANEL_M);
    const int nt = rr / PANEL_M;
    const long m0 = (long)mt * BM;
    const long n0 = (long)nt * BN;

    // ---------------- cp.async load slots (incremental pointers) ----------
    // A: 2048 16B chunks / 512 threads = 4 each; B: 1024 / 512 = 2 each.
    const float* aP[4];
    uint32_t aDst[4];
    #pragma unroll
    for (int c = 0; c < 4; c++) {
        int idx = c * NTHREADS + tid;
        int row = idx >> 3, cb = idx & 7;
        aP[c] = A + (m0 + row) * (long)KDIM + cb * 4;
        uint32_t bo = (uint32_t)(row * 128 + cb * 16);
        aDst[c] = bo ^ ((bo >> 3) & 0x70);
    }
    const float* bP[2];
    uint32_t bDst[2];
    #pragma unroll
    for (int c = 0; c < 2; c++) {
        int idx = c * NTHREADS + tid;
        int row = idx >> 3, cb = idx & 7;
        bP[c] = B + (n0 + row) * (long)KDIM + cb * 4;
        uint32_t bo = (uint32_t)(row * 128 + cb * 16);
        bDst[c] = A_BYTES + (bo ^ ((bo >> 3) & 0x70));
    }

    // ---------------- ldmatrix address components ----------------
    const uint32_t aRowOff = (uint32_t)((wr * 64 + (lid & 15)) * 128);
    const uint32_t aSwz = (uint32_t)((lid & 7) << 4);
    const uint32_t aHi = (uint32_t)(((lid >> 4) & 1) * 16);
    const uint32_t bRowOff =
        (uint32_t)(A_BYTES + (wc * 32 + (lid & 7) + ((lid >> 4) & 1) * 8) * 128);
    const uint32_t bSwz = (uint32_t)((lid & 7) << 4);
    const uint32_t bHi = (uint32_t)(((lid >> 3) & 1) * 16);

    float acc[4][4][4];
    #pragma unroll
    for (int mi = 0; mi < 4; mi++)
        #pragma unroll
        for (int ni = 0; ni < 4; ni++)
            #pragma unroll
            for (int q = 0; q < 4; q++) acc[mi][ni][q] = 0.0f;

    // ---------------- prologue: fill stages 0..2 (tiles 0..2) ----------------
    #pragma unroll
    for (int t = 0; t < STAGES - 1; t++) {
        uint32_t sb = sbase + t * STAGE_BYTES;
        #pragma unroll
        for (int c = 0; c < 4; c++) { cpa16(sb + aDst[c], aP[c]); aP[c] += BK; }
        #pragma unroll
        for (int c = 0; c < 2; c++) { cpa16(sb + bDst[c], bP[c]); bP[c] += BK; }
        asm volatile("cp.async.commit_group;");
    }

    // rdBase = stage t%4 (read this iter); wrBase = stage (t+3)%4 (prefetch).
    uint32_t rdBase = sbase;
    uint32_t wrBase = sbase + (STAGES - 1) * STAGE_BYTES;

    // ---------------- main loop: ONE barrier per k-tile ----------------
    #pragma unroll 1
    for (int t = 0; t < KTILES; t++) {
        // Tile t's commit group is complete once <= STAGES-2 groups pend.
        asm volatile("cp.async.wait_group %0;" :: "n"(STAGES - 2));
        // Publishes tile t's smem to all warps AND orders last iter's reads
        // of stage (t-1)%4 before this iter's prefetch overwrites it.
        __syncthreads();

        if (t < KTILES - (STAGES - 1)) {
            #pragma unroll
            for (int c = 0; c < 4; c++) { cpa16(wrBase + aDst[c], aP[c]); aP[c] += BK; }
            #pragma unroll
            for (int c = 0; c < 2; c++) { cpa16(wrBase + bDst[c], bP[c]); bP[c] += BK; }
        }
        asm volatile("cp.async.commit_group;");

        const uint32_t sb = rdBase;
        #pragma unroll
        for (int ks = 0; ks < 4; ks++) {
            // B fragments: 2 ldmatrix.x4 -> b[4][2], rounded to tf32 (rna).
            uint32_t b[4][2];
            {
                const uint32_t xB = ((uint32_t)(ks * 32) | bHi) ^ bSwz;
                ldsm_x4(b[0][0], b[0][1], b[1][0], b[1][1], sb + bRowOff + xB);
                ldsm_x4(b[2][0], b[2][1], b[3][0], b[3][1], sb + bRowOff + 2048 + xB);
                #pragma unroll
                for (int ni = 0; ni < 4; ni++) {
                    b[ni][0] = f2tf32(b[ni][0]);
                    b[ni][1] = f2tf32(b[ni][1]);
                }
            }
            // A fragments: raw fp32 bits (HW truncates to tf32).
            const uint32_t xA = ((uint32_t)(ks * 32) | aHi) ^ aSwz;
            #pragma unroll
            for (int mi = 0; mi < 4; mi++) {
                uint32_t a0, a1, a2, a3;
                ldsm_x4(a0, a1, a2, a3, sb + aRowOff + mi * 2048 + xA);
                #pragma unroll
                for (int ni = 0; ni < 4; ni++)
                    mma_tf32(acc[mi][ni][0], acc[mi][ni][1],
                             acc[mi][ni][2], acc[mi][ni][3],
                             a0, a1, a2, a3, b[ni][0], b[ni][1]);
            }
        }

        // Rotate stage bases (no modulo).
        wrBase = rdBase;
        rdBase += STAGE_BYTES;
        if (rdBase == sbase + STAGES * STAGE_BYTES) rdBase = sbase;
    }

    // ---------------- epilogue: direct STG.64 ----------------
    {
        const int g = lid >> 2;
        const int tig = lid & 3;
        const long sec = n0 >> 12;                 // q/k/v section (BN | 4096)
        const long colbase = (n0 & 4095) + wc * 32 + tig * 2;
        float* Ob = O + sec * ((long)MDIM * 4096);
        #pragma unroll
        for (int mi = 0; mi < 4; mi++) {
            const long r = m0 + wr * 64 + mi * 16 + g;
            float* p0 = Ob + r * 4096 + colbase;
            float* p1 = p0 + 8 * 4096;
            #pragma unroll
            for (int ni = 0; ni < 4; ni++) {
                *reinterpret_cast<float2*>(p0 + ni * 8) =
                    make_float2(acc[mi][ni][0], acc[mi][ni][1]);
                *reinterpret_cast<float2*>(p1 + ni * 8) =
                    make_float2(acc[mi][ni][2], acc[mi][ni][3]);
            }
        }
    }
}

extern "C" void kernel_launch(void* const* d_in, const int* in_sizes, int n_in,
                              void* d_out, int out_size) {
    (void)in_sizes; (void)n_in; (void)out_size;
    const float* hs = (const float*)d_in[0];   // hidden_states [4,4096,4096]
    const float* w  = (const float*)d_in[1];   // qkv_proj [12288,4096]
    // d_in[2] = position_ids — RoPE is an identity stub; unused.
    float* out = (float*)d_out;

    cudaFuncSetAttribute(qkv_tf32_kernel,
                         cudaFuncAttributeMaxDynamicSharedMemorySize, SMEM_TOTAL);
    qkv_tf32_kernel<<<M_TILES * N_TILES, NTHREADS, SMEM_TOTAL>>>(hs, w, out);
}

// round 8
// speedup vs baseline: 1.0956x; 1.0956x over previous
#include <cuda_runtime.h>
#include <cstdint>

// ============================================================================
// QKV projection as one tf32 mma.sync GEMM (baseline PTX; tcgen05 rejected by
// this toolchain's .target sm_103):
//   C[16384, 12288] = A[16384,4096] @ B[12288,4096]^T
// A = hidden_states (row-major), B = qkv_proj (row-major), RoPE = identity.
// Output: 3 column sections of C -> q|k|v concatenated fp32 regions.
//
// R7 vs R4 (7219us best, tensor 75%, occ 25%) and R5/R6 (7580us REGRESSION):
//  - loop skeleton reverted to R4's proven two-barrier multistage order
//  - 2 CTAs/SM: BM=128, BN=128, 256 thr, 3 stages x 32KB = 96KB smem/CTA.
//    The co-resident CTA covers the other's wait_group/bar.sync bubbles
//    (R5 showed reordering alone can't: 1 CTA has nothing else to run).
//  - keep cvt.rna.tf32 on B fragments (rel_err ~4.7e-4, 2x margin).
// ============================================================================

static constexpr int MDIM = 16384;
static constexpr int NDIM = 12288;
static constexpr int KDIM = 4096;

static constexpr int BM = 128;
static constexpr int BN = 128;
static constexpr int BK = 32;                  // 32 fp32 = 128 B row
static constexpr int KTILES = KDIM / BK;       // 128
static constexpr int STAGES = 3;
static constexpr int A_BYTES = BM * BK * 4;    // 16 KB
static constexpr int B_BYTES = BN * BK * 4;    // 16 KB
static constexpr int STAGE_BYTES = A_BYTES + B_BYTES;      // 32 KB
static constexpr int SMEM_TOTAL = STAGES * STAGE_BYTES;    // 96 KB -> 2 CTA/SM
static constexpr int M_TILES = MDIM / BM;      // 128
static constexpr int N_TILES = NDIM / BN;      // 96
static constexpr int PANEL_M = 16;             // L2 rasterization panel
static constexpr int NTHREADS = 256;

__device__ __forceinline__ uint32_t smem_u32(const void* p) {
    uint32_t a;
    asm("{ .reg .u64 t; cvta.to.shared.u64 t, %1; cvt.u32.u64 %0, t; }"
        : "=r"(a) : "l"(p));
    return a;
}

__device__ __forceinline__ void cpa16(uint32_t dst, const void* src) {
    asm volatile("cp.async.cg.shared.global [%0], [%1], 16;" :: "r"(dst), "l"(src));
}

__device__ __forceinline__ uint32_t f2tf32(uint32_t bits) {
    uint32_t o;
    asm("cvt.rna.tf32.f32 %0, %1;" : "=r"(o) : "f"(__uint_as_float(bits)));
    return o;
}

__device__ __forceinline__ void ldsm_x4(uint32_t& r0, uint32_t& r1,
                                        uint32_t& r2, uint32_t& r3, uint32_t addr) {
    asm volatile("ldmatrix.sync.aligned.m8n8.x4.shared.b16 {%0,%1,%2,%3}, [%4];"
                 : "=r"(r0), "=r"(r1), "=r"(r2), "=r"(r3) : "r"(addr));
}

__device__ __forceinline__ void mma_tf32(float& c0, float& c1, float& c2, float& c3,
                                         uint32_t a0, uint32_t a1, uint32_t a2,
                                         uint32_t a3, uint32_t b0, uint32_t b1) {
    asm volatile(
        "mma.sync.aligned.m16n8k8.row.col.f32.tf32.tf32.f32 "
        "{%0,%1,%2,%3}, {%4,%5,%6,%7}, {%8,%9}, {%0,%1,%2,%3};"
        : "+f"(c0), "+f"(c1), "+f"(c2), "+f"(c3)
        : "r"(a0), "r"(a1), "r"(a2), "r"(a3), "r"(b0), "r"(b1));
}

__global__ void __launch_bounds__(NTHREADS, 2)
qkv_tf32_kernel(const float* __restrict__ A, const float* __restrict__ B,
                float* __restrict__ O) {
    extern __shared__ __align__(1024) char smem[];
    const uint32_t sbase = smem_u32(smem);
    const int tid = threadIdx.x;
    const int wid = tid >> 5;
    const int lid = tid & 31;
    const int wr = wid & 1;    // warp row: m-offset wr*64 (2 rows)
    const int wc = wid >> 1;   // warp col: n-offset wc*32 (4 cols)

    // Panel-swizzled tile mapping (16 m-tiles fast, n slow) for L2 reuse.
    const int bid = blockIdx.x;
    const int panel = bid / (PANEL_M * N_TILES);
    const int rr = bid % (PANEL_M * N_TILES);
    const int mt = panel * PANEL_M + (rr % PANEL_M);
    const int nt = rr / PANEL_M;
    const long m0 = (long)mt * BM;
    const long n0 = (long)nt * BN;

    // ---------------- cp.async load slots (incremental pointers) ----------
    // A: 1024 16B chunks / 256 threads = 4 each; B: 1024 / 256 = 4 each.
    const float* aP[4];
    uint32_t aDst[4];
    #pragma unroll
    for (int c = 0; c < 4; c++) {
        int idx = c * NTHREADS + tid;
        int row = idx >> 3, cb = idx & 7;
        aP[c] = A + (m0 + row) * (long)KDIM + cb * 4;
        uint32_t bo = (uint32_t)(row * 128 + cb * 16);
        aDst[c] = bo ^ ((bo >> 3) & 0x70);
    }
    const float* bP[4];
    uint32_t bDst[4];
    #pragma unroll
    for (int c = 0; c < 4; c++) {
        int idx = c * NTHREADS + tid;
        int row = idx >> 3, cb = idx & 7;
        bP[c] = B + (n0 + row) * (long)KDIM + cb * 4;
        uint32_t bo = (uint32_t)(row * 128 + cb * 16);
        bDst[c] = A_BYTES + (bo ^ ((bo >> 3) & 0x70));
    }

    // ---------------- ldmatrix address components ----------------
    const uint32_t aRowOff = (uint32_t)((wr * 64 + (lid & 15)) * 128);
    const uint32_t aSwz = (uint32_t)((lid & 7) << 4);
    const uint32_t aHi = (uint32_t)(((lid >> 4) & 1) * 16);
    const uint32_t bRowOff =
        (uint32_t)(A_BYTES + (wc * 32 + (lid & 7) + ((lid >> 4) & 1) * 8) * 128);
    const uint32_t bSwz = (uint32_t)((lid & 7) << 4);
    const uint32_t bHi = (uint32_t)(((lid >> 3) & 1) * 16);

    float acc[4][4][4];
    #pragma unroll
    for (int mi = 0; mi < 4; mi++)
        #pragma unroll
        for (int ni = 0; ni < 4; ni++)
            #pragma unroll
            for (int q = 0; q < 4; q++) acc[mi][ni][q] = 0.0f;

    // ---------------- prologue: fill stages 0,1 (tiles 0,1) ----------------
    #pragma unroll
    for (int t = 0; t < STAGES - 1; t++) {
        uint32_t sb = sbase + t * STAGE_BYTES;
        #pragma unroll
        for (int c = 0; c < 4; c++) { cpa16(sb + aDst[c], aP[c]); aP[c] += BK; }
        #pragma unroll
        for (int c = 0; c < 4; c++) { cpa16(sb + bDst[c], bP[c]); bP[c] += BK; }
        asm volatile("cp.async.commit_group;");
    }

    // rdBase = stage t%3 (read this iter); wrBase = stage (t+2)%3 (prefetch).
    uint32_t rdBase = sbase;
    uint32_t wrBase = sbase + (STAGES - 1) * STAGE_BYTES;

    // ---------------- main loop (R4 proven skeleton) ----------------
    #pragma unroll 1
    for (int t = 0; t < KTILES; t++) {
        // Guard stage reuse: wrBase == stage read at iter t-1.
        __syncthreads();

        if (t < KTILES - (STAGES - 1)) {
            #pragma unroll
            for (int c = 0; c < 4; c++) { cpa16(wrBase + aDst[c], aP[c]); aP[c] += BK; }
            #pragma unroll
            for (int c = 0; c < 4; c++) { cpa16(wrBase + bDst[c], bP[c]); bP[c] += BK; }
        }
        asm volatile("cp.async.commit_group;");
        asm volatile("cp.async.wait_group %0;" :: "n"(STAGES - 1));  // tile t done
        __syncthreads();

        const uint32_t sb = rdBase;
        #pragma unroll
        for (int ks = 0; ks < 4; ks++) {
            // B fragments: 2 ldmatrix.x4 -> b[4][2], rounded to tf32 (rna).
            uint32_t b[4][2];
            {
                const uint32_t xB = ((uint32_t)(ks * 32) | bHi) ^ bSwz;
                ldsm_x4(b[0][0], b[0][1], b[1][0], b[1][1], sb + bRowOff + xB);
                ldsm_x4(b[2][0], b[2][1], b[3][0], b[3][1], sb + bRowOff + 2048 + xB);
                #pragma unroll
                for (int ni = 0; ni < 4; ni++) {
                    b[ni][0] = f2tf32(b[ni][0]);
                    b[ni][1] = f2tf32(b[ni][1]);
                }
            }
            // A fragments: raw fp32 bits (HW truncates to tf32).
            const uint32_t xA = ((uint32_t)(ks * 32) | aHi) ^ aSwz;
            #pragma unroll
            for (int mi = 0; mi < 4; mi++) {
                uint32_t a0, a1, a2, a3;
                ldsm_x4(a0, a1, a2, a3, sb + aRowOff + mi * 2048 + xA);
                #pragma unroll
                for (int ni = 0; ni < 4; ni++)
                    mma_tf32(acc[mi][ni][0], acc[mi][ni][1],
                             acc[mi][ni][2], acc[mi][ni][3],
                             a0, a1, a2, a3, b[ni][0], b[ni][1]);
            }
        }

        // Rotate stage bases (no modulo).
        wrBase = rdBase;
        rdBase += STAGE_BYTES;
        if (rdBase == sbase + STAGES * STAGE_BYTES) rdBase = sbase;
    }

    // ---------------- epilogue: direct STG.64 ----------------
    {
        const int g = lid >> 2;
        const int tig = lid & 3;
        const long sec = n0 >> 12;                 // q/k/v section (BN | 4096)
        const long colbase = (n0 & 4095) + wc * 32 + tig * 2;
        float* Ob = O + sec * ((long)MDIM * 4096);
        #pragma unroll
        for (int mi = 0; mi < 4; mi++) {
            const long r = m0 + wr * 64 + mi * 16 + g;
            float* p0 = Ob + r * 4096 + colbase;
            float* p1 = p0 + 8 * 4096;
            #pragma unroll
            for (int ni = 0; ni < 4; ni++) {
                *reinterpret_cast<float2*>(p0 + ni * 8) =
                    make_float2(acc[mi][ni][0], acc[mi][ni][1]);
                *reinterpret_cast<float2*>(p1 + ni * 8) =
                    make_float2(acc[mi][ni][2], acc[mi][ni][3]);
            }
        }
    }
}

extern "C" void kernel_launch(void* const* d_in, const int* in_sizes, int n_in,
                              void* d_out, int out_size) {
    (void)in_sizes; (void)n_in; (void)out_size;
    const float* hs = (const float*)d_in[0];   // hidden_states [4,4096,4096]
    const float* w  = (const float*)d_in[1];   // qkv_proj [12288,4096]
    // d_in[2] = position_ids — RoPE is an identity stub; unused.
    float* out = (float*)d_out;

    cudaFuncSetAttribute(qkv_tf32_kernel,
                         cudaFuncAttributeMaxDynamicSharedMemorySize, SMEM_TOTAL);
    qkv_tf32_kernel<<<M_TILES * N_TILES, NTHREADS, SMEM_TOTAL>>>(hs, w, out);
}

// round 10
// speedup vs baseline: 1.1289x; 1.0304x over previous
#include <cuda_runtime.h>
#include <cstdint>

// ============================================================================
// QKV projection as one tf32 mma.sync GEMM (baseline PTX; tcgen05 rejected by
// this toolchain's .target sm_103):
//   C[16384, 12288] = A[16384,4096] @ B[12288,4096]^T
// A = hidden_states (row-major), B = qkv_proj (row-major), RoPE = identity.
// Output: 3 column sections of C -> q|k|v concatenated fp32 regions.
//
// R8 vs R7 (6918us, tensor 78.3%, alu 12.4%, occ 16/64 warps):
//  - mainloop has ZERO __syncthreads: per-stage mbarrier producer/consumer
//    pipeline (cp.async.mbarrier.arrive.noinc -> full[s], arrive -> empty[s]).
//    Warps start computing a tile the instant its stage is full, instead of
//    rendezvousing twice per k-tile; only the 3-ahead prefetch is gated.
//  - single A/B pointer + compile-time chunk offsets (swizzle is invariant
//    under row+=32, so smem dsts are base + c*4096): alu 12.4% -> ~5%.
//  - keep cvt.rna.tf32 on B fragments (rel_err 4.7e-4, 2x margin).
// ============================================================================

static constexpr int MDIM = 16384;
static constexpr int NDIM = 12288;
static constexpr int KDIM = 4096;

static constexpr int BM = 128;
static constexpr int BN = 128;
static constexpr int BK = 32;                  // 32 fp32 = 128 B row
static constexpr int KTILES = KDIM / BK;       // 128
static constexpr int STAGES = 3;
static constexpr int A_BYTES = BM * BK * 4;    // 16 KB
static constexpr int B_BYTES = BN * BK * 4;    // 16 KB
static constexpr int STAGE_BYTES = A_BYTES + B_BYTES;      // 32 KB
static constexpr int SMEM_HDR = 1024;          // mbarriers
static constexpr int SMEM_TOTAL = SMEM_HDR + STAGES * STAGE_BYTES;  // ~97KB -> 2 CTA/SM
static constexpr int M_TILES = MDIM / BM;      // 128
static constexpr int N_TILES = NDIM / BN;      // 96
static constexpr int PANEL_M = 16;             // L2 rasterization panel
static constexpr int NTHREADS = 256;

__device__ __forceinline__ uint32_t smem_u32(const void* p) {
    uint32_t a;
    asm("{ .reg .u64 t; cvta.to.shared.u64 t, %1; cvt.u32.u64 %0, t; }"
        : "=r"(a) : "l"(p));
    return a;
}

__device__ __forceinline__ void cpa16(uint32_t dst, const void* src) {
    asm volatile("cp.async.cg.shared.global [%0], [%1], 16;" :: "r"(dst), "l"(src));
}

__device__ __forceinline__ uint32_t f2tf32(uint32_t bits) {
    uint32_t o;
    asm("cvt.rna.tf32.f32 %0, %1;" : "=r"(o) : "f"(__uint_as_float(bits)));
    return o;
}

__device__ __forceinline__ void ldsm_x4(uint32_t& r0, uint32_t& r1,
                                        uint32_t& r2, uint32_t& r3, uint32_t addr) {
    asm volatile("ldmatrix.sync.aligned.m8n8.x4.shared.b16 {%0,%1,%2,%3}, [%4];"
                 : "=r"(r0), "=r"(r1), "=r"(r2), "=r"(r3) : "r"(addr));
}

__device__ __forceinline__ void mma_tf32(float& c0, float& c1, float& c2, float& c3,
                                         uint32_t a0, uint32_t a1, uint32_t a2,
                                         uint32_t a3, uint32_t b0, uint32_t b1) {
    asm volatile(
        "mma.sync.aligned.m16n8k8.row.col.f32.tf32.tf32.f32 "
        "{%0,%1,%2,%3}, {%4,%5,%6,%7}, {%8,%9}, {%0,%1,%2,%3};"
        : "+f"(c0), "+f"(c1), "+f"(c2), "+f"(c3)
        : "r"(a0), "r"(a1), "r"(a2), "r"(a3), "r"(b0), "r"(b1));
}

__device__ __forceinline__ void mbar_init(uint32_t addr, uint32_t cnt) {
    asm volatile("mbarrier.init.shared.b64 [%0], %1;" :: "r"(addr), "r"(cnt) : "memory");
}

__device__ __forceinline__ void mbar_arrive(uint32_t addr) {
    asm volatile("mbarrier.arrive.shared.b64 _, [%0];" :: "r"(addr) : "memory");
}

// Arrive on mbarrier once this thread's prior cp.asyncs complete (count preset).
__device__ __forceinline__ void cpasync_arrive(uint32_t addr) {
    asm volatile("cp.async.mbarrier.arrive.noinc.shared.b64 [%0];" :: "r"(addr) : "memory");
}

__device__ __forceinline__ void mbar_wait_acq(uint32_t addr, uint32_t parity) {
    asm volatile(
        "{\n\t.reg .pred P;\n\t"
        "WA_%=:\n\t"
        "mbarrier.try_wait.parity.acquire.cta.shared::cta.b64 P, [%0], %1, 0x989680;\n\t"
        "@P bra.uni WAD_%=;\n\t"
        "bra.uni WA_%=;\n\t"
        "WAD_%=:\n\t}"
        :: "r"(addr), "r"(parity) : "memory");
}

__device__ __forceinline__ void mbar_wait_rlx(uint32_t addr, uint32_t parity) {
    asm volatile(
        "{\n\t.reg .pred P;\n\t"
        "WR_%=:\n\t"
        "mbarrier.try_wait.parity.relaxed.cta.shared::cta.b64 P, [%0], %1, 0x989680;\n\t"
        "@P bra.uni WRD_%=;\n\t"
        "bra.uni WR_%=;\n\t"
        "WRD_%=:\n\t}"
        :: "r"(addr), "r"(parity) : "memory");
}

__global__ void __launch_bounds__(NTHREADS, 2)
qkv_tf32_kernel(const float* __restrict__ A, const float* __restrict__ B,
                float* __restrict__ O) {
    extern __shared__ __align__(1024) char smem[];
    const uint32_t sbase = smem_u32(smem);
    const int tid = threadIdx.x;
    const int wid = tid >> 5;
    const int lid = tid & 31;
    const int wr = wid & 1;    // warp row: m-offset wr*64
    const int wc = wid >> 1;   // warp col: n-offset wc*32

    // mbarriers: full[s] at sbase + s*16, empty[s] at sbase + s*16 + 8.
    if (tid == 0) {
        #pragma unroll
        for (int s = 0; s < STAGES; s++) {
            mbar_init(sbase + s * 16, NTHREADS);
            mbar_init(sbase + s * 16 + 8, NTHREADS);
        }
    }

    // Panel-swizzled tile mapping (16 m-tiles fast, n slow) for L2 reuse.
    const int bid = blockIdx.x;
    const int panel = bid / (PANEL_M * N_TILES);
    const int rr = bid % (PANEL_M * N_TILES);
    const int mt = panel * PANEL_M + (rr % PANEL_M);
    const int nt = rr / PANEL_M;
    const long m0 = (long)mt * BM;
    const long n0 = (long)nt * BN;

    // ---------------- cp.async base addresses ----------------
    // Chunk c handles row (c*32 + tid/8), 16B-col (tid&7). Swizzled smem dst
    // for chunk c is dst0 + c*4096 (row+=32 leaves swizzle bits untouched);
    // gmem src is src0 + c*32*KDIM.
    const int row0 = tid >> 3, cb0 = tid & 7;
    const float* aP = A + (m0 + row0) * (long)KDIM + cb0 * 4;
    const float* bP = B + (n0 + row0) * (long)KDIM + cb0 * 4;
    uint32_t bo0 = (uint32_t)(row0 * 128 + cb0 * 16);
    const uint32_t aDst0 = bo0 ^ ((bo0 >> 3) & 0x70);
    const uint32_t bDst0 = A_BYTES + aDst0;

    // ---------------- ldmatrix address components ----------------
    const uint32_t aRowOff = (uint32_t)((wr * 64 + (lid & 15)) * 128);
    const uint32_t aSwz = (uint32_t)((lid & 7) << 4);
    const uint32_t aHi = (uint32_t)(((lid >> 4) & 1) * 16);
    const uint32_t bRowOff =
        (uint32_t)(A_BYTES + (wc * 32 + (lid & 7) + ((lid >> 4) & 1) * 8) * 128);
    const uint32_t bSwz = (uint32_t)((lid & 7) << 4);
    const uint32_t bHi = (uint32_t)(((lid >> 3) & 1) * 16);

    float acc[4][4][4];
    #pragma unroll
    for (int mi = 0; mi < 4; mi++)
        #pragma unroll
        for (int ni = 0; ni < 4; ni++)
            #pragma unroll
            for (int q = 0; q < 4; q++) acc[mi][ni][q] = 0.0f;

    // mbarrier init must be visible before any arrive.
    __syncthreads();

    // ---------------- prologue: fill all 3 stages (tiles 0..2) ----------------
    #pragma unroll
    for (int t = 0; t < STAGES; t++) {
        uint32_t sa = sbase + SMEM_HDR + t * STAGE_BYTES;
        #pragma unroll
        for (int c = 0; c < 4; c++) {
            cpa16(sa + aDst0 + c * 4096, aP + (long)c * 32 * KDIM);
            cpa16(sa + bDst0 + c * 4096, bP + (long)c * 32 * KDIM);
        }
        cpasync_arrive(sbase + t * 16);   // full[t] when this thread's cpas land
        aP += BK; bP += BK;
    }

    // ---------------- main loop: no block barriers ----------------
    uint32_t rdBase = sbase + SMEM_HDR;
    int s = 0;        // stage index
    uint32_t p = 0;   // parity (reuse cycle & 1)

    #pragma unroll 1
    for (int t = 0; t < KTILES; t++) {
        const uint32_t mbFull = sbase + s * 16;
        const uint32_t mbEmpty = mbFull + 8;

        // Wait until every thread's cp.asyncs for this stage completed.
        mbar_wait_acq(mbFull, p);

        const uint32_t sb = rdBase;
        #pragma unroll
        for (int ks = 0; ks < 4; ks++) {
            // B fragments: 2 ldmatrix.x4 -> b[4][2], rounded to tf32 (rna).
            uint32_t b[4][2];
            {
                const uint32_t xB = ((uint32_t)(ks * 32) | bHi) ^ bSwz;
                ldsm_x4(b[0][0], b[0][1], b[1][0], b[1][1], sb + bRowOff + xB);
                ldsm_x4(b[2][0], b[2][1], b[3][0], b[3][1], sb + bRowOff + 2048 + xB);
                #pragma unroll
                for (int ni = 0; ni < 4; ni++) {
                    b[ni][0] = f2tf32(b[ni][0]);
                    b[ni][1] = f2tf32(b[ni][1]);
                }
            }
            // A fragments: raw fp32 bits (HW truncates to tf32).
            const uint32_t xA = ((uint32_t)(ks * 32) | aHi) ^ aSwz;
            #pragma unroll
            for (int mi = 0; mi < 4; mi++) {
                uint32_t a0, a1, a2, a3;
                ldsm_x4(a0, a1, a2, a3, sb + aRowOff + mi * 2048 + xA);
                #pragma unroll
                for (int ni = 0; ni < 4; ni++)
                    mma_tf32(acc[mi][ni][0], acc[mi][ni][1],
                             acc[mi][ni][2], acc[mi][ni][3],
                             a0, a1, a2, a3, b[ni][0], b[ni][1]);
            }
        }

        // Done reading stage s for this phase.
        mbar_arrive(mbEmpty);

        // Refill this stage with tile t+3 once ALL threads consumed tile t.
        if (t < KTILES - STAGES) {
            mbar_wait_rlx(mbEmpty, p);     // post-wait writes are async-proxy
            #pragma unroll
            for (int c = 0; c < 4; c++) {
                cpa16(sb + aDst0 + c * 4096, aP + (long)c * 32 * KDIM);
                cpa16(sb + bDst0 + c * 4096, bP + (long)c * 32 * KDIM);
            }
            cpasync_arrive(mbFull);
            aP += BK; bP += BK;
        }

        // Advance stage cursor.
        s++;
        rdBase += STAGE_BYTES;
        if (s == STAGES) { s = 0; p ^= 1; rdBase = sbase + SMEM_HDR; }
    }

    // ---------------- epilogue: direct STG.64 ----------------
    {
        const int g = lid >> 2;
        const int tig = lid & 3;
        const long sec = n0 >> 12;                 // q/k/v section (BN | 4096)
        const long colbase = (n0 & 4095) + wc * 32 + tig * 2;
        float* Ob = O + sec * ((long)MDIM * 4096);
        #pragma unroll
        for (int mi = 0; mi < 4; mi++) {
            const long r = m0 + wr * 64 + mi * 16 + g;
            float* p0 = Ob + r * 4096 + colbase;
            float* p1 = p0 + 8 * 4096;
            #pragma unroll
            for (int ni = 0; ni < 4; ni++) {
                *reinterpret_cast<float2*>(p0 + ni * 8) =
                    make_float2(acc[mi][ni][0], acc[mi][ni][1]);
                *reinterpret_cast<float2*>(p1 + ni * 8) =
                    make_float2(acc[mi][ni][2], acc[mi][ni][3]);
            }
        }
    }
}

extern "C" void kernel_launch(void* const* d_in, const int* in_sizes, int n_in,
                              void* d_out, int out_size) {
    (void)in_sizes; (void)n_in; (void)out_size;
    const float* hs = (const float*)d_in[0];   // hidden_states [4,4096,4096]
    const float* w  = (const float*)d_in[1];   // qkv_proj [12288,4096]
    // d_in[2] = position_ids — RoPE is an identity stub; unused.
    float* out = (float*)d_out;

    cudaFuncSetAttribute(qkv_tf32_kernel,
                         cudaFuncAttributeMaxDynamicSharedMemorySize, SMEM_TOTAL);
    qkv_tf32_kernel<<<M_TILES * N_TILES, NTHREADS, SMEM_TOTAL>>>(hs, w, out);
}